// round 1
// baseline (speedup 1.0000x reference)
#include <cuda_runtime.h>

// Problem constants
#define YY 5
#define NN 200000
#define GG 128
#define II 128
#define RR 3
#define BB 1024
#define KK 64

// Scratch (no cudaMalloc allowed)
__device__ float g_mean[(size_t)YY * BB * RR * GG];   // A matrix: [y*B+b][r*G+g]
__device__ float g_weff[RR * GG * II];                // Weff:     [r*G+g][i]
__device__ int   g_is64;                              // neighbor/count dtype flag

// ---------------------------------------------------------------------------
// Detect whether neighbors/counts are int64 or int32.
// Values are in [0, 200000) so if stored as little-endian int64, every odd
// 32-bit word is zero. Sample 4096 odd words; OR-reduce.
// ---------------------------------------------------------------------------
__global__ void detect_dtype_kernel(const unsigned int* __restrict__ nbr_u32) {
    __shared__ unsigned int s_or;
    if (threadIdx.x == 0) s_or = 0u;
    __syncthreads();
    unsigned int v = 0u;
    for (int i = threadIdx.x; i < 4096; i += blockDim.x)
        v |= nbr_u32[2 * i + 1];
    atomicOr(&s_or, v);
    __syncthreads();
    if (threadIdx.x == 0) g_is64 = (s_or == 0u) ? 1 : 0;
}

// ---------------------------------------------------------------------------
// Build effective weights: Weff[0] = sum(W_cite, axis=0); Weff[1..2] = W_rel[1..2]
// Layouts are identical linear fp32 [r][g][i].
// ---------------------------------------------------------------------------
__global__ void build_weff_kernel(const float* __restrict__ Wrel,
                                  const float* __restrict__ Wcite) {
    int idx = blockIdx.x * blockDim.x + threadIdx.x;
    if (idx >= RR * GG * II) return;
    int r  = idx / (GG * II);
    int gi = idx - r * (GG * II);
    float v;
    if (r == 0)
        v = Wcite[gi] + Wcite[GG * II + gi] + Wcite[2 * GG * II + gi];
    else
        v = Wrel[idx];
    g_weff[idx] = v;
}

// ---------------------------------------------------------------------------
// Gather + masked mean: one CTA per (y, r, b); thread = g column.
// mean[y,r,b,g] = (1/max(count,1)) * sum_{k<count} emb[y, nbr[y,r,b,k], g]
// Written to g_mean[(y*B+b)*384 + r*128 + g] (GEMM A layout).
// ---------------------------------------------------------------------------
__global__ void gather_mean_kernel(const float* __restrict__ emb,
                                   const void* __restrict__ nbr,
                                   const void* __restrict__ cnt) {
    const int b = blockIdx.x;
    const int r = blockIdx.y;
    const int y = blockIdx.z;
    const int tid = threadIdx.x;   // 0..127 (g)
    const int is64 = g_is64;

    const long long lin = ((long long)y * RR + r) * BB + b;

    int count;
    if (is64) count = (int)((const long long*)cnt)[lin];
    else      count = ((const int*)cnt)[lin];

    __shared__ int sidx[KK];
    if (tid < KK) {
        if (is64) sidx[tid] = (int)((const long long*)nbr)[lin * KK + tid];
        else      sidx[tid] = ((const int*)nbr)[lin * KK + tid];
    }
    __syncthreads();

    const float* e = emb + (size_t)y * NN * GG + tid;

    float acc = 0.0f;
    int k = 0;
    for (; k + 4 <= count; k += 4) {
        float v0 = e[(size_t)sidx[k + 0] * GG];
        float v1 = e[(size_t)sidx[k + 1] * GG];
        float v2 = e[(size_t)sidx[k + 2] * GG];
        float v3 = e[(size_t)sidx[k + 3] * GG];
        acc += (v0 + v1) + (v2 + v3);
    }
    for (; k < count; ++k)
        acc += e[(size_t)sidx[k] * GG];

    const float inv = 1.0f / (float)(count > 0 ? count : 1);
    g_mean[((size_t)y * BB + b) * (RR * GG) + r * GG + tid] = acc * inv;
}

// ---------------------------------------------------------------------------
// SGEMM: out[5120, 128] = g_mean[5120, 384] @ g_weff[384, 128]
// Tile BM=32 x BN=128, BK=32, 256 threads. Warp handles 4 rows x 128 cols:
//   A fragment is a warp-uniform smem broadcast (conflict-free),
//   W fragment is a coalesced float4 row read (conflict-free).
// 160 CTAs ~ one full wave on 148 SMs.
// ---------------------------------------------------------------------------
#define BM 32
#define BN 128
#define BK 32

__global__ void gemm_kernel(float* __restrict__ out) {
    __shared__ __align__(16) float Ast[BK][BM + 4];  // transposed A, pad 36 floats/row
    __shared__ __align__(16) float Ws[BK][BN];

    const int tid = threadIdx.x;        // 0..255
    const int tr  = tid >> 5;           // warp id 0..7 -> rows tr*4 .. tr*4+3
    const int tc  = tid & 31;           // lane -> cols tc*4 .. tc*4+3
    const int rowbase = blockIdx.x * BM;

    float4 acc0 = make_float4(0.f, 0.f, 0.f, 0.f);
    float4 acc1 = acc0, acc2 = acc0, acc3 = acc0;

    // A global load mapping: 32 rows x 32 k per chunk, one float4 per thread
    const int arow = tid >> 3;          // 0..31
    const int acol = (tid & 7) * 4;     // 0,4,...,28
    const float* Aptr = g_mean + (size_t)(rowbase + arow) * (RR * GG);

    for (int k0 = 0; k0 < RR * GG; k0 += BK) {
        // stage A (transposed)
        float4 a4 = *(const float4*)(Aptr + k0 + acol);
        Ast[acol + 0][arow] = a4.x;
        Ast[acol + 1][arow] = a4.y;
        Ast[acol + 2][arow] = a4.z;
        Ast[acol + 3][arow] = a4.w;
        // stage W: 32x128 floats = 1024 float4s, 4 per thread
        #pragma unroll
        for (int j = 0; j < 4; ++j) {
            int l  = tid + j * 256;      // float4 linear index
            int wk = l >> 5;
            int wc = (l & 31) * 4;
            *(float4*)&Ws[wk][wc] =
                *(const float4*)(g_weff + (size_t)(k0 + wk) * BN + wc);
        }
        __syncthreads();

        #pragma unroll
        for (int kk = 0; kk < BK; ++kk) {
            float4 a = *(const float4*)&Ast[kk][tr * 4];   // warp-uniform broadcast
            float4 w = *(const float4*)&Ws[kk][tc * 4];    // conflict-free
            acc0.x = fmaf(a.x, w.x, acc0.x); acc0.y = fmaf(a.x, w.y, acc0.y);
            acc0.z = fmaf(a.x, w.z, acc0.z); acc0.w = fmaf(a.x, w.w, acc0.w);
            acc1.x = fmaf(a.y, w.x, acc1.x); acc1.y = fmaf(a.y, w.y, acc1.y);
            acc1.z = fmaf(a.y, w.z, acc1.z); acc1.w = fmaf(a.y, w.w, acc1.w);
            acc2.x = fmaf(a.z, w.x, acc2.x); acc2.y = fmaf(a.z, w.y, acc2.y);
            acc2.z = fmaf(a.z, w.z, acc2.z); acc2.w = fmaf(a.z, w.w, acc2.w);
            acc3.x = fmaf(a.w, w.x, acc3.x); acc3.y = fmaf(a.w, w.y, acc3.y);
            acc3.z = fmaf(a.w, w.z, acc3.z); acc3.w = fmaf(a.w, w.w, acc3.w);
        }
        __syncthreads();
    }

    const int row = rowbase + tr * 4;
    float* o = out + (size_t)row * BN + tc * 4;
    *(float4*)(o + 0 * BN) = acc0;
    *(float4*)(o + 1 * BN) = acc1;
    *(float4*)(o + 2 * BN) = acc2;
    *(float4*)(o + 3 * BN) = acc3;
}

// ---------------------------------------------------------------------------
// kernel_launch: detect dtype -> build Weff -> gather means -> GEMM
// Inputs (metadata order): embeddings f32, W_rel f32, W_cite f32,
//                          neighbors int (32 or 64), counts int, train_year
// Output: f32 [Y*B*I] contiguous (reshape in reference is a view).
// ---------------------------------------------------------------------------
extern "C" void kernel_launch(void* const* d_in, const int* in_sizes, int n_in,
                              void* d_out, int out_size) {
    const float* emb   = (const float*)d_in[0];
    const float* Wrel  = (const float*)d_in[1];
    const float* Wcite = (const float*)d_in[2];
    const void*  nbr   = d_in[3];
    const void*  cnt   = d_in[4];
    float* out = (float*)d_out;

    detect_dtype_kernel<<<1, 256>>>((const unsigned int*)nbr);
    build_weff_kernel<<<(RR * GG * II + 255) / 256, 256>>>(Wrel, Wcite);

    dim3 g1(BB, RR, YY);   // z (year) slowest -> year locality in L2
    gather_mean_kernel<<<g1, 128>>>(emb, nbr, cnt);

    gemm_kernel<<<(YY * BB) / BM, 256>>>(out);
}

// round 2
// speedup vs baseline: 1.2412x; 1.2412x over previous
#include <cuda_runtime.h>

// Problem constants
#define YY 5
#define NN 200000
#define GG 128
#define II 128
#define RR 3
#define BB 1024
#define KK 64
#define KTOT (RR * GG)   // 384

// Scratch (no cudaMalloc allowed)
__device__ float g_mean[(size_t)YY * BB * KTOT];   // A matrix: [y*B+b][r*G+g]
__device__ float g_weff[KTOT * II];                // Weff:     [r*G+g][i]
__device__ int   g_is64;                           // neighbor/count dtype flag

// ---------------------------------------------------------------------------
// prep: build Weff (blocks 0..191) + detect int64 vs int32 (last block).
// int64 detection: values < 2e5, so every odd 32-bit word of an int64 buffer
// is zero. Sample 4096 odd words, OR-reduce.
// ---------------------------------------------------------------------------
__global__ void prep_kernel(const float* __restrict__ Wrel,
                            const float* __restrict__ Wcite,
                            const unsigned int* __restrict__ nbr_u32) {
    if (blockIdx.x == 192) {
        __shared__ unsigned int s_or;
        if (threadIdx.x == 0) s_or = 0u;
        __syncthreads();
        unsigned int v = 0u;
        for (int i = threadIdx.x; i < 4096; i += blockDim.x)
            v |= nbr_u32[2 * i + 1];
        atomicOr(&s_or, v);
        __syncthreads();
        if (threadIdx.x == 0) g_is64 = (s_or == 0u) ? 1 : 0;
        return;
    }
    int idx = blockIdx.x * 256 + threadIdx.x;   // < 49152
    int r  = idx / (GG * II);
    int gi = idx - r * (GG * II);
    float v;
    if (r == 0)
        v = Wcite[gi] + Wcite[GG * II + gi] + Wcite[2 * GG * II + gi];
    else
        v = Wrel[idx];
    g_weff[idx] = v;
}

// ---------------------------------------------------------------------------
// Gather + masked mean: one CTA per (y, r, b); thread = g column.
// mean[y,r,b,g] = (1/max(count,1)) * sum_{k<count} emb[y, nbr[y,r,b,k], g]
// ---------------------------------------------------------------------------
__global__ void __launch_bounds__(128) gather_mean_kernel(
        const float* __restrict__ emb,
        const void* __restrict__ nbr,
        const void* __restrict__ cnt) {
    const int b = blockIdx.x;
    const int r = blockIdx.y;
    const int y = blockIdx.z;
    const int tid = threadIdx.x;   // 0..127 (g)
    const int is64 = g_is64;

    const long long lin = ((long long)y * RR + r) * BB + b;

    int count;
    if (is64) count = (int)((const long long*)cnt)[lin];
    else      count = ((const int*)cnt)[lin];

    __shared__ int sidx[KK];
    if (tid < KK) {
        if (is64) sidx[tid] = (int)((const long long*)nbr)[lin * KK + tid];
        else      sidx[tid] = ((const int*)nbr)[lin * KK + tid];
    }
    __syncthreads();

    const float* e = emb + (size_t)y * NN * GG + tid;

    float acc = 0.0f;
    int k = 0;
    for (; k + 8 <= count; k += 8) {
        float v0 = e[(size_t)sidx[k + 0] * GG];
        float v1 = e[(size_t)sidx[k + 1] * GG];
        float v2 = e[(size_t)sidx[k + 2] * GG];
        float v3 = e[(size_t)sidx[k + 3] * GG];
        float v4 = e[(size_t)sidx[k + 4] * GG];
        float v5 = e[(size_t)sidx[k + 5] * GG];
        float v6 = e[(size_t)sidx[k + 6] * GG];
        float v7 = e[(size_t)sidx[k + 7] * GG];
        acc += ((v0 + v1) + (v2 + v3)) + ((v4 + v5) + (v6 + v7));
    }
    for (; k < count; ++k)
        acc += e[(size_t)sidx[k] * GG];

    const float inv = 1.0f / (float)(count > 0 ? count : 1);
    g_mean[((size_t)y * BB + b) * KTOT + r * GG + tid] = acc * inv;
}

// ---------------------------------------------------------------------------
// SGEMM: out[5120, 128] = g_mean[5120, 384] @ g_weff[384, 128]
// 128 threads (4 warps), BM=32 x BN=128, BK=32, 160 CTAs.
// Warp w owns rows w*8..w*8+7; lane owns cols lane*4..lane*4+3.
// Accumulators packed as f32x2 over ROW pairs so the A LDS.128 (4 adjacent
// rows) reinterprets as two packed operands at zero cost; only W duplicates.
// Double-buffered smem, register prefetch, one sync per chunk.
// ---------------------------------------------------------------------------
#define BM 32
#define BN 128
#define BK 32
#define NCHUNK (KTOT / BK)   // 12
#define APAD 8               // A row stride 40 floats = 160B -> 16B aligned

__device__ __forceinline__ unsigned long long fma2(unsigned long long a,
                                                   unsigned long long b,
                                                   unsigned long long c) {
    unsigned long long d;
    asm("fma.rn.f32x2 %0, %1, %2, %3;" : "=l"(d) : "l"(a), "l"(b), "l"(c));
    return d;
}
__device__ __forceinline__ unsigned long long dup2(float x) {
    unsigned long long d;
    unsigned int u = __float_as_uint(x);
    asm("mov.b64 %0, {%1, %1};" : "=l"(d) : "r"(u));
    return d;
}
__device__ __forceinline__ float2 unpk2(unsigned long long p) {
    unsigned int lo, hi;
    asm("mov.b64 {%0, %1}, %2;" : "=r"(lo), "=r"(hi) : "l"(p));
    return make_float2(__uint_as_float(lo), __uint_as_float(hi));
}

__global__ void __launch_bounds__(128, 1) gemm_kernel(float* __restrict__ out) {
    __shared__ __align__(16) float Ast[2][BK][BM + APAD];  // transposed A
    __shared__ __align__(16) float Ws[2][BK][BN];

    const int tid  = threadIdx.x;
    const int w    = tid >> 5;    // warp 0..3 -> rows w*8..w*8+7
    const int lane = tid & 31;    // cols lane*4..lane*4+3
    const int rowbase = blockIdx.x * BM;

    unsigned long long acc[4][4];   // [rowpair][col]
    #pragma unroll
    for (int i = 0; i < 4; ++i)
        #pragma unroll
        for (int j = 0; j < 4; ++j) acc[i][j] = 0ull;

    const float* Ag = g_mean + (size_t)rowbase * KTOT;

    float4 pa[2];
    float4 pw[8];

    // prologue: load + stage chunk 0
    #pragma unroll
    for (int j = 0; j < 2; ++j) {
        int l = tid + j * 128;
        pa[j] = *(const float4*)(Ag + (size_t)(l >> 3) * KTOT + ((l & 7) << 2));
    }
    #pragma unroll
    for (int j = 0; j < 8; ++j) {
        int l = tid + j * 128;
        pw[j] = *(const float4*)(g_weff + (size_t)(l >> 5) * BN + ((l & 31) << 2));
    }
    #pragma unroll
    for (int j = 0; j < 2; ++j) {
        int l = tid + j * 128;
        int rr = l >> 3, kc = (l & 7) << 2;
        Ast[0][kc + 0][rr] = pa[j].x;
        Ast[0][kc + 1][rr] = pa[j].y;
        Ast[0][kc + 2][rr] = pa[j].z;
        Ast[0][kc + 3][rr] = pa[j].w;
    }
    #pragma unroll
    for (int j = 0; j < 8; ++j) {
        int l = tid + j * 128;
        *(float4*)&Ws[0][l >> 5][(l & 31) << 2] = pw[j];
    }
    __syncthreads();

    for (int c = 0; c < NCHUNK; ++c) {
        const int buf = c & 1;
        const bool more = (c + 1 < NCHUNK);
        if (more) {
            const int k0 = (c + 1) * BK;
            #pragma unroll
            for (int j = 0; j < 2; ++j) {
                int l = tid + j * 128;
                pa[j] = *(const float4*)(Ag + (size_t)(l >> 3) * KTOT + k0 + ((l & 7) << 2));
            }
            #pragma unroll
            for (int j = 0; j < 8; ++j) {
                int l = tid + j * 128;
                pw[j] = *(const float4*)(g_weff + (size_t)(k0 + (l >> 5)) * BN + ((l & 31) << 2));
            }
        }

        #pragma unroll
        for (int kk = 0; kk < BK; ++kk) {
            ulonglong2 aP0 = *(const ulonglong2*)&Ast[buf][kk][w * 8];      // rows 0-3
            ulonglong2 aP1 = *(const ulonglong2*)&Ast[buf][kk][w * 8 + 4];  // rows 4-7
            float4 w4 = *(const float4*)&Ws[buf][kk][lane * 4];
            unsigned long long wd0 = dup2(w4.x), wd1 = dup2(w4.y);
            unsigned long long wd2 = dup2(w4.z), wd3 = dup2(w4.w);

            acc[0][0] = fma2(aP0.x, wd0, acc[0][0]);
            acc[0][1] = fma2(aP0.x, wd1, acc[0][1]);
            acc[0][2] = fma2(aP0.x, wd2, acc[0][2]);
            acc[0][3] = fma2(aP0.x, wd3, acc[0][3]);
            acc[1][0] = fma2(aP0.y, wd0, acc[1][0]);
            acc[1][1] = fma2(aP0.y, wd1, acc[1][1]);
            acc[1][2] = fma2(aP0.y, wd2, acc[1][2]);
            acc[1][3] = fma2(aP0.y, wd3, acc[1][3]);
            acc[2][0] = fma2(aP1.x, wd0, acc[2][0]);
            acc[2][1] = fma2(aP1.x, wd1, acc[2][1]);
            acc[2][2] = fma2(aP1.x, wd2, acc[2][2]);
            acc[2][3] = fma2(aP1.x, wd3, acc[2][3]);
            acc[3][0] = fma2(aP1.y, wd0, acc[3][0]);
            acc[3][1] = fma2(aP1.y, wd1, acc[3][1]);
            acc[3][2] = fma2(aP1.y, wd2, acc[3][2]);
            acc[3][3] = fma2(aP1.y, wd3, acc[3][3]);
        }

        if (more) {
            const int nbuf = buf ^ 1;
            #pragma unroll
            for (int j = 0; j < 2; ++j) {
                int l = tid + j * 128;
                int rr = l >> 3, kc = (l & 7) << 2;
                Ast[nbuf][kc + 0][rr] = pa[j].x;
                Ast[nbuf][kc + 1][rr] = pa[j].y;
                Ast[nbuf][kc + 2][rr] = pa[j].z;
                Ast[nbuf][kc + 3][rr] = pa[j].w;
            }
            #pragma unroll
            for (int j = 0; j < 8; ++j) {
                int l = tid + j * 128;
                *(float4*)&Ws[nbuf][l >> 5][(l & 31) << 2] = pw[j];
            }
            __syncthreads();
        }
    }

    // epilogue: unpack row pairs, write float4 per row
    const int row0 = rowbase + w * 8;
    float* o = out + (size_t)row0 * BN + lane * 4;
    #pragma unroll
    for (int rp = 0; rp < 4; ++rp) {
        float2 c0 = unpk2(acc[rp][0]);
        float2 c1 = unpk2(acc[rp][1]);
        float2 c2 = unpk2(acc[rp][2]);
        float2 c3 = unpk2(acc[rp][3]);
        *(float4*)(o + (size_t)(2 * rp) * BN)     = make_float4(c0.x, c1.x, c2.x, c3.x);
        *(float4*)(o + (size_t)(2 * rp + 1) * BN) = make_float4(c0.y, c1.y, c2.y, c3.y);
    }
}

// ---------------------------------------------------------------------------
// kernel_launch
// ---------------------------------------------------------------------------
extern "C" void kernel_launch(void* const* d_in, const int* in_sizes, int n_in,
                              void* d_out, int out_size) {
    const float* emb   = (const float*)d_in[0];
    const float* Wrel  = (const float*)d_in[1];
    const float* Wcite = (const float*)d_in[2];
    const void*  nbr   = d_in[3];
    const void*  cnt   = d_in[4];
    float* out = (float*)d_out;

    prep_kernel<<<193, 256>>>(Wrel, Wcite, (const unsigned int*)nbr);

    dim3 g1(BB, RR, YY);   // z (year) slowest -> year locality in L2
    gather_mean_kernel<<<g1, 128>>>(emb, nbr, cnt);

    gemm_kernel<<<(YY * BB) / BM, 128>>>(out);
}